// round 14
// baseline (speedup 1.0000x reference)
#include <cuda_runtime.h>
#include <cstdint>
#include <cstddef>

// ---------------- static device scratch ----------------
__device__ float g_z0[128 * 128];      // accumulator for feat@Wm0 (zeroed by kB after read)
__device__ float g_sum[3 * 256];       // per-stage BN stats accumulators (zeroed by kA)
__device__ unsigned g_barcnt[8];       // grid barrier counters (zeroed by kA; fallback path)

// ---------------- packed f32x2 FMA helpers (sm_100+) ----------------
__device__ __forceinline__ void ffma2(unsigned long long& d,
                                      unsigned long long a,
                                      unsigned long long b) {
    asm("fma.rn.f32x2 %0, %1, %2, %0;" : "+l"(d) : "l"(a), "l"(b));
}
__device__ __forceinline__ unsigned long long bcast2(float a) {
    unsigned long long r;
    unsigned u = __float_as_uint(a);
    asm("mov.b64 %0, {%1, %1};" : "=l"(r) : "r"(u));
    return r;
}
__device__ __forceinline__ void unpack2(float& lo, float& hi, unsigned long long v) {
    unsigned u0, u1;
    asm("mov.b64 {%0, %1}, %2;" : "=r"(u0), "=r"(u1) : "l"(v));
    lo = __uint_as_float(u0);
    hi = __uint_as_float(u1);
}

// =====================================================================
// Kernel A:
//   blocks 0..127   : per-graph GNN -> pooled -> pooled@Wm0[0:128] -> +g_z0
//   blocks 128..287 : split-K GEMM feat[x|ew]@Wm0[128:], 32 rows/block,
//                     DUAL independent k-chains (MLP x2) -> +g_z0
// =====================================================================
#define KA_SMEM_FLOATS (64*65 + 1024 + 1024 + 2048 + 8192 + 64 + 64 + 128)

__global__ void __launch_bounds__(256, 3) kA(
    const float* __restrict__ x,  const float* __restrict__ ew,
    const float* __restrict__ W1, const float* __restrict__ b1,
    const float* __restrict__ W2, const float* __restrict__ b2,
    const float* __restrict__ Wm0)
{
    extern __shared__ float sm[];
    const int t = threadIdx.x;
    const int bid = blockIdx.x;

    if (bid < 128) {
        const int g = bid;
        float* Es   = sm;             // [64][65]
        float* xd   = Es + 64 * 65;   // [64][16]
        float* y    = xd + 1024;      // [64][16] / reduce scratch 256
        float* W1s  = y + 1024;       // [16][128]
        float* h1   = W1s + 2048;     // [64][128] (reused as pm[8][128])
        float* dinv = h1 + 8192;      // [64]
        float* cv   = dinv + 64;      // [64]
        float* u    = cv + 64;        // [128] pooled

        if (g == 0) {
            if (t < 8) g_barcnt[t] = 0u;
#pragma unroll
            for (int i = 0; i < 3; i++) g_sum[i * 256 + t] = 0.f;
        }

        const float4* ew4 = (const float4*)(ew + (size_t)g * 4096);
#pragma unroll
        for (int it = 0; it < 4; it++) {
            int idx = t + it * 256;
            float4 v = ew4[idx];
            int i = idx >> 4, j = (idx & 15) << 2;
            float* p = Es + i * 65 + j;
            p[0] = v.x; p[1] = v.y; p[2] = v.z; p[3] = v.w;
        }
        ((float4*)xd)[t] = ((const float4*)(x + (size_t)g * 1024))[t];
        ((float4*)W1s)[t]       = ((const float4*)W1)[t];
        ((float4*)W1s)[t + 256] = ((const float4*)W1)[t + 256];
        __syncthreads();

        if (t < 64) {
            float s = 0.f;
#pragma unroll 8
            for (int i = 0; i < 64; i++) s += Es[i * 65 + t];
            dinv[t] = (s > 0.f) ? rsqrtf(s) : 0.f;
        }
        __syncthreads();

#pragma unroll
        for (int it = 0; it < 4; it++) {
            int idx = t + it * 256;
            xd[idx] *= dinv[idx >> 4];
        }
        if (t < 64) {
            float s = 0.f;
#pragma unroll 8
            for (int j = 0; j < 64; j++) s += Es[t * 65 + j] * dinv[j];
            cv[t] = s * dinv[t];
        }
        __syncthreads();

        {   // y = dinv .* (E^T xd)   — FFMA2
            int j = t >> 2;
            int f0 = (t & 3) << 2;
            unsigned long long a01 = 0ULL, a23 = 0ULL;
#pragma unroll 8
            for (int i = 0; i < 64; i++) {
                unsigned long long e2 = bcast2(Es[i * 65 + j]);
                ulonglong2 xr = *(const ulonglong2*)(xd + i * 16 + f0);
                ffma2(a01, e2, xr.x);
                ffma2(a23, e2, xr.y);
            }
            float dj = dinv[j];
            float v0, v1, v2, v3;
            unpack2(v0, v1, a01);
            unpack2(v2, v3, a23);
            float* yp = y + j * 16 + f0;
            yp[0] = v0 * dj; yp[1] = v1 * dj; yp[2] = v2 * dj; yp[3] = v3 * dj;
        }
        __syncthreads();

        {   // h1 = relu(y @ W1 + b1)   — FFMA2
            const int warp = t >> 5, lane = t & 31, c = lane << 2;
            unsigned long long acc2[8][2];
#pragma unroll
            for (int rr = 0; rr < 8; rr++) { acc2[rr][0] = 0ULL; acc2[rr][1] = 0ULL; }
#pragma unroll
            for (int k = 0; k < 16; k++) {
                ulonglong2 w2 = *(const ulonglong2*)(W1s + k * 128 + c);
#pragma unroll
                for (int rr = 0; rr < 8; rr++) {
                    unsigned long long a2 = bcast2(y[(warp * 8 + rr) * 16 + k]);
                    ffma2(acc2[rr][0], a2, w2.x);
                    ffma2(acc2[rr][1], a2, w2.y);
                }
            }
            float4 bv = __ldg((const float4*)(b1 + c));
#pragma unroll
            for (int rr = 0; rr < 8; rr++) {
                float v0, v1, v2, v3;
                unpack2(v0, v1, acc2[rr][0]);
                unpack2(v2, v3, acc2[rr][1]);
                float4 v;
                v.x = fmaxf(v0 + bv.x, 0.f);
                v.y = fmaxf(v1 + bv.y, 0.f);
                v.z = fmaxf(v2 + bv.z, 0.f);
                v.w = fmaxf(v3 + bv.w, 0.f);
                *(float4*)(h1 + (warp * 8 + rr) * 128 + c) = v;
            }
        }
        __syncthreads();

        {   // u-half reduce
            int c = t & 127, h = t >> 7;
            float s = 0.f;
#pragma unroll 8
            for (int i = h * 32; i < h * 32 + 32; i++)
                s = fmaf(cv[i], h1[i * 128 + c], s);
            y[t] = s;
        }
        __syncthreads();
        if (t < 128) u[t] = (y[t] + y[t + 128]) * (1.f / 64.f);
        __syncthreads();

        {   // pooled pre-relu: u @ W2 — 4 independent chains, full unroll (MLP)
            int c = t & 127, h = t >> 7;
            const float* Wp = W2 + (size_t)(h * 64) * 128 + c;
            const float* up = u + h * 64;
            float s0 = 0.f, s1 = 0.f, s2 = 0.f, s3 = 0.f;
#pragma unroll
            for (int f = 0; f < 64; f += 4) {
                float w0 = __ldg(Wp + (size_t)(f + 0) * 128);
                float w1 = __ldg(Wp + (size_t)(f + 1) * 128);
                float w2v = __ldg(Wp + (size_t)(f + 2) * 128);
                float w3 = __ldg(Wp + (size_t)(f + 3) * 128);
                s0 = fmaf(up[f + 0], w0, s0);
                s1 = fmaf(up[f + 1], w1, s1);
                s2 = fmaf(up[f + 2], w2v, s2);
                s3 = fmaf(up[f + 3], w3, s3);
            }
            y[t] = (s0 + s1) + (s2 + s3);
        }
        __syncthreads();
        if (t < 128)
            u[t] = fmaxf(y[t] + y[t + 128] + __ldg(b2 + t), 0.f);  // pooled (relu'd)
        __syncthreads();

        {   // pooled @ Wm0[0:128] partial   — FFMA2
            int cq = t & 31, seg = t >> 5;      // 8 k-segments of 16
            unsigned long long a0 = 0ULL, a1 = 0ULL;
            const float* base = Wm0 + (size_t)(seg * 16) * 128 + (cq << 2);
#pragma unroll
            for (int kk = 0; kk < 16; kk++) {
                ulonglong2 w2 = __ldg((const ulonglong2*)(base + (size_t)kk * 128));
                unsigned long long p2 = bcast2(u[seg * 16 + kk]);
                ffma2(a0, p2, w2.x);
                ffma2(a1, p2, w2.y);
            }
            float v0, v1, v2, v3;
            unpack2(v0, v1, a0);
            unpack2(v2, v3, a1);
            *(float4*)(h1 + seg * 128 + (cq << 2)) = make_float4(v0, v1, v2, v3);
        }
        __syncthreads();
        if (t < 128) {
            float s = 0.f;
#pragma unroll
            for (int seg = 0; seg < 8; seg++) s += h1[seg * 128 + t];
            atomicAdd(&g_z0[(size_t)g * 128 + t], s);
        }
    } else {
        // ----- split-K mlp0: 40 chunks of K=128, 32 rows/block -----
        // DUAL k-chains (k and k+64) -> two independent LDG streams (MLP x2).
        const int id = bid - 128;       // 0..159
        const int kc = id >> 2;         // 0..39
        const int rt = id & 3;          // row tile of 32
        const int r0 = rt << 5;
        float* fs = sm;                 // [32][128]

#pragma unroll
        for (int it = 0; it < 4; it++) {
            int idx = t + it * 256;     // 0..1023 float4
            int r = idx >> 5;
            int q4 = (idx & 31) << 2;
            float4 v;
            if (kc < 8) {
                v = *(const float4*)(x + (size_t)(r0 + r) * 1024 + (kc << 7) + q4);
                v.x = fmaxf(v.x, 0.f); v.y = fmaxf(v.y, 0.f);
                v.z = fmaxf(v.z, 0.f); v.w = fmaxf(v.w, 0.f);
            } else {
                v = *(const float4*)(ew + (size_t)(r0 + r) * 4096 + ((kc - 8) << 7) + q4);
            }
            *(float4*)(fs + r * 128 + q4) = v;
        }
        __syncthreads();

        const int warp = t >> 5, lane = t & 31, c = lane << 2;
        const int koff = 128 + (kc << 7);
        unsigned long long accA[4][2], accB[4][2];
#pragma unroll
        for (int i = 0; i < 4; i++) {
            accA[i][0] = 0ULL; accA[i][1] = 0ULL;
            accB[i][0] = 0ULL; accB[i][1] = 0ULL;
        }

        const float* WrowA = Wm0 + (size_t)koff * 128 + c;
        const float* WrowB = WrowA + (size_t)64 * 128;
        const float* fsw = fs + (warp * 4) * 128;
#pragma unroll 4
        for (int k = 0; k < 64; k++) {
            ulonglong2 wA = __ldg((const ulonglong2*)(WrowA + (size_t)k * 128));
            ulonglong2 wB = __ldg((const ulonglong2*)(WrowB + (size_t)k * 128));
#pragma unroll
            for (int i = 0; i < 4; i++) {
                unsigned long long aA = bcast2(fsw[i * 128 + k]);
                unsigned long long aB = bcast2(fsw[i * 128 + 64 + k]);
                ffma2(accA[i][0], aA, wA.x);
                ffma2(accA[i][1], aA, wA.y);
                ffma2(accB[i][0], aB, wB.x);
                ffma2(accB[i][1], aB, wB.y);
            }
        }
#pragma unroll
        for (int i = 0; i < 4; i++) {
            float a0, a1, a2, a3, b0, b1, b2v, b3;
            unpack2(a0, a1, accA[i][0]);
            unpack2(a2, a3, accA[i][1]);
            unpack2(b0, b1, accB[i][0]);
            unpack2(b2v, b3, accB[i][1]);
            float* dst = g_z0 + (size_t)(r0 + warp * 4 + i) * 128 + c;
            atomicAdd(dst + 0, a0 + b0);
            atomicAdd(dst + 1, a1 + b1);
            atomicAdd(dst + 2, a2 + b2v);
            atomicAdd(dst + 3, a3 + b3);
        }
    }
}

// =====================================================================
// Kernel B: 16-CTA row-split tail (8 rows/CTA, 512 threads). R13 version.
// =====================================================================
__device__ __forceinline__ uint32_t smem_u32(const void* p) {
    uint32_t a;
    asm("{ .reg .u64 tt; cvta.to.shared.u64 tt, %1; cvt.u32.u64 %0, tt; }"
        : "=r"(a) : "l"(p));
    return a;
}

__device__ __forceinline__ void bulk_cp(uint32_t sdst, const void* gsrc,
                                        uint32_t bytes, uint32_t mbar) {
    asm volatile(
        "cp.async.bulk.shared::cluster.global.mbarrier::complete_tx::bytes "
        "[%0], [%1], %2, [%3];"
        :: "r"(sdst), "l"(gsrc), "r"(bytes), "r"(mbar) : "memory");
}

__device__ __forceinline__ void mbar_expect(uint32_t mbar, uint32_t bytes) {
    asm volatile("mbarrier.arrive.expect_tx.shared.b64 _, [%0], %1;"
                 :: "r"(mbar), "r"(bytes) : "memory");
}

__device__ __forceinline__ void mbar_wait(uint32_t mbar, uint32_t parity) {
    asm volatile(
        "{\n\t"
        ".reg .pred P1;\n\t"
        "WL_%=:\n\t"
        "mbarrier.try_wait.parity.acquire.cta.shared::cta.b64 P1, [%0], %1, 0x989680;\n\t"
        "@P1 bra.uni WD_%=;\n\t"
        "bra.uni WL_%=;\n\t"
        "WD_%=:\n\t"
        "}"
        :: "r"(mbar), "r"(parity) : "memory");
}

// SMEM float offsets (three weight buffers)
#define SW0   0                          // Wm1: 16384 floats
#define SW1   16384                      // Wm2: 16384 floats
#define SW2   32768                      // Wout: 8192 floats
#define SZ    40960                      // z [8][132]: 1056
#define SQ    (40960 + 1056)             // q [8][132]: 1056
#define SRED  (40960 + 2112)             // redk: 8192
#define SABN  (SRED + 8192)              // abn: 128
#define SBBN  (SABN + 128)               // bbn: 128
#define SPAR  (SBBN + 128)               // params: 1088
#define STOT  (SPAR + 1088)              // 52608 floats
#define KB_SMEM_BYTES (STOT * 4 + 32)    // 210464 B (+ three mbarriers)

// GEMM: redk[ks][8][128] = q[8rows] x W, ks-split 8
__device__ __forceinline__ void gemm128_v2(const float* __restrict__ q,
                                           const float* __restrict__ W,
                                           float* __restrict__ redk, int t)
{
    const int ks   = t >> 6;            // 0..7
    const int half = (t >> 5) & 1;      // row group
    const int c4   = (t & 31) << 2;
    const int rb   = half * 4;
    const float* Wp = W + (ks * 16) * 128 + c4;
    float4 a0 = {0,0,0,0}, a1 = {0,0,0,0}, a2 = {0,0,0,0}, a3 = {0,0,0,0};
#pragma unroll
    for (int kq = 0; kq < 4; kq++) {
        float4 q0 = *(const float4*)(q + (rb + 0) * 132 + ks * 16 + kq * 4);
        float4 q1 = *(const float4*)(q + (rb + 1) * 132 + ks * 16 + kq * 4);
        float4 q2 = *(const float4*)(q + (rb + 2) * 132 + ks * 16 + kq * 4);
        float4 q3 = *(const float4*)(q + (rb + 3) * 132 + ks * 16 + kq * 4);
#pragma unroll
        for (int dk = 0; dk < 4; dk++) {
            float4 w = *(const float4*)(Wp + (kq * 4 + dk) * 128);
            float e0 = (&q0.x)[dk], e1 = (&q1.x)[dk];
            float e2 = (&q2.x)[dk], e3 = (&q3.x)[dk];
            a0.x = fmaf(e0, w.x, a0.x); a0.y = fmaf(e0, w.y, a0.y);
            a0.z = fmaf(e0, w.z, a0.z); a0.w = fmaf(e0, w.w, a0.w);
            a1.x = fmaf(e1, w.x, a1.x); a1.y = fmaf(e1, w.y, a1.y);
            a1.z = fmaf(e1, w.z, a1.z); a1.w = fmaf(e1, w.w, a1.w);
            a2.x = fmaf(e2, w.x, a2.x); a2.y = fmaf(e2, w.y, a2.y);
            a2.z = fmaf(e2, w.z, a2.z); a2.w = fmaf(e2, w.w, a2.w);
            a3.x = fmaf(e3, w.x, a3.x); a3.y = fmaf(e3, w.y, a3.y);
            a3.z = fmaf(e3, w.z, a3.z); a3.w = fmaf(e3, w.w, a3.w);
        }
    }
    float* rp = redk + ks * 1024 + rb * 128 + c4;
    *(float4*)(rp)       = a0;
    *(float4*)(rp + 128) = a1;
    *(float4*)(rp + 256) = a2;
    *(float4*)(rp + 384) = a3;
}

__global__ void __launch_bounds__(512, 1) kB(
    const float* __restrict__ bm0,
    const float* __restrict__ g0,   const float* __restrict__ be0,
    const float* __restrict__ Wm1,  const float* __restrict__ bm1,
    const float* __restrict__ g1,   const float* __restrict__ be1,
    const float* __restrict__ Wm2,  const float* __restrict__ bm2,
    const float* __restrict__ g2,   const float* __restrict__ be2,
    const float* __restrict__ Wout, const float* __restrict__ bout,
    float* __restrict__ out, int use_cluster)
{
    extern __shared__ float sm[];
    float* W0   = sm + SW0;
    float* W1b  = sm + SW1;
    float* W2b  = sm + SW2;
    float* z    = sm + SZ;
    float* q    = sm + SQ;
    float* redk = sm + SRED;
    float* abn  = sm + SABN;
    float* bbn  = sm + SBBN;
    float* sGB  = sm + SPAR;            // [3][256] gamma|beta
    float* sBias = sGB + 768;           // [2][128] bm1|bm2
    float* sBout = sBias + 256;         // [64]
    const uint32_t mb0 = smem_u32(sm + STOT);
    const uint32_t mb1 = mb0 + 8;
    const uint32_t mb2 = mb0 + 16;

    const int t   = threadIdx.x;
    const int cta = blockIdx.x;          // 0..15
    const int r0  = cta << 3;            // first global row

    if (t == 0) {
        asm volatile("mbarrier.init.shared.b64 [%0], 1;" :: "r"(mb0) : "memory");
        asm volatile("mbarrier.init.shared.b64 [%0], 1;" :: "r"(mb1) : "memory");
        asm volatile("mbarrier.init.shared.b64 [%0], 1;" :: "r"(mb2) : "memory");
        asm volatile("fence.proxy.async.shared::cta;" ::: "memory");
        mbar_expect(mb0, 65536u);
        bulk_cp(smem_u32(W0), Wm1, 65536u, mb0);
        mbar_expect(mb1, 65536u);
        bulk_cp(smem_u32(W1b), Wm2, 65536u, mb1);
        mbar_expect(mb2, 32768u);
        bulk_cp(smem_u32(W2b), Wout, 32768u, mb2);
    }

    // ---- entry: z = g_z0(rows) + bm0; re-zero g_z0 rows; preload params ----
    if (t < 256) {
        int r = t >> 5, c4 = (t & 31) << 2;
        float* gp = g_z0 + (size_t)(r0 + r) * 128 + c4;
        float4 v = *(float4*)gp;
        *(float4*)gp = make_float4(0.f, 0.f, 0.f, 0.f);
        float4 b = __ldg((const float4*)(bm0 + c4));
        v.x += b.x; v.y += b.y; v.z += b.z; v.w += b.w;
        *(float4*)(z + r * 132 + c4) = v;
    } else {
        int u = t - 256;                 // 0..255
        int c = u & 127;
        if (u < 128) {
            sGB[c]       = __ldg(g0 + c);
            sGB[128 + c] = __ldg(be0 + c);
            sGB[512 + c] = __ldg(g2 + c);
            sGB[640 + c] = __ldg(be2 + c);
            sBias[c]     = __ldg(bm1 + c);
        } else {
            sGB[256 + c] = __ldg(g1 + c);
            sGB[384 + c] = __ldg(be1 + c);
            sBias[128 + c] = __ldg(bm2 + c);
            if (c < 64) sBout[c] = __ldg(bout + c);
        }
    }
    __syncthreads();

#pragma unroll 1
    for (int s = 0; s < 3; s++) {
        // local column stats over this CTA's 8 rows -> global accumulators
        if (t < 128) {
            float su = 0.f, sq = 0.f;
#pragma unroll
            for (int r = 0; r < 8; r++) {
                float v = fmaxf(z[r * 132 + t], 0.f);
                su += v; sq = fmaf(v, v, sq);
            }
            atomicAdd(&g_sum[s * 256 + t], su);
            atomicAdd(&g_sum[s * 256 + 128 + t], sq);
        }

        // ---- grid-wide barrier ----
        if (use_cluster) {
            __syncthreads();
            asm volatile("barrier.cluster.arrive.aligned;" ::: "memory");
            asm volatile("barrier.cluster.wait.aligned;" ::: "memory");
        } else {
            __threadfence();
            __syncthreads();
            if (t == 0) {
                atomicAdd(&g_barcnt[s], 1u);
                unsigned v;
                do {
                    asm volatile("ld.acquire.gpu.global.u32 %0, [%1];"
                                 : "=r"(v) : "l"(g_barcnt + s) : "memory");
                } while (v < 16u);
            }
            __syncthreads();
        }

        // fold BN coefficients (2 global loads; params from SMEM)
        if (t < 128) {
            float su = g_sum[s * 256 + t];
            float sq = g_sum[s * 256 + 128 + t];
            float mu   = su * (1.f / 128.f);
            float var  = fmaf(sq, 1.f / 128.f, -mu * mu);
            float rstd = rsqrtf(var + 1e-5f);
            float a = sGB[s * 256 + t] * rstd;
            abn[t] = a;
            bbn[t] = sGB[s * 256 + 128 + t] - mu * a;
        }
        __syncthreads();

        // q = abn * relu(z) + bbn
        if (t < 256) {
            int r = t >> 5, c4 = (t & 31) << 2;
            float4 zv = *(const float4*)(z + r * 132 + c4);
            float4 a4 = *(const float4*)(abn + c4);
            float4 b4 = *(const float4*)(bbn + c4);
            float4 qv;
            qv.x = fmaf(a4.x, fmaxf(zv.x, 0.f), b4.x);
            qv.y = fmaf(a4.y, fmaxf(zv.y, 0.f), b4.y);
            qv.z = fmaf(a4.z, fmaxf(zv.z, 0.f), b4.z);
            qv.w = fmaf(a4.w, fmaxf(zv.w, 0.f), b4.w);
            *(float4*)(q + r * 132 + c4) = qv;
        }
        // wait for this stage's weights (streamed at kernel start)
        if (t == 0) {
            if (s == 0)      mbar_wait(mb0, 0);
            else if (s == 1) mbar_wait(mb1, 0);
            else             mbar_wait(mb2, 0);
        }
        __syncthreads();

        if (s < 2) {
            gemm128_v2(q, (s == 0) ? W0 : W1b, redk, t);
            __syncthreads();
#pragma unroll
            for (int io = 0; io < 2; io++) {
                int o = t + io * 512;
                int r = o >> 7, c = o & 127;
                float v = sBias[s * 128 + c];
#pragma unroll
                for (int ks = 0; ks < 8; ks++) v += redk[ks * 1024 + o];
                z[r * 132 + c] = v;
            }
            __syncthreads();
        } else {
            // final GEMM: out = q @ Wout + bout   (Wout in W2b, 128x64)
            const int ks   = t >> 6;
            const int half = (t >> 5) & 1;
            const int c2   = (t & 31) << 1;
            const int rb   = half * 4;
            const float* Wp = W2b + (ks * 16) * 64 + c2;
            float2 a0 = {0,0}, a1 = {0,0}, a2 = {0,0}, a3 = {0,0};
#pragma unroll
            for (int kq = 0; kq < 4; kq++) {
                float4 q0 = *(const float4*)(q + (rb + 0) * 132 + ks * 16 + kq * 4);
                float4 q1 = *(const float4*)(q + (rb + 1) * 132 + ks * 16 + kq * 4);
                float4 q2 = *(const float4*)(q + (rb + 2) * 132 + ks * 16 + kq * 4);
                float4 q3 = *(const float4*)(q + (rb + 3) * 132 + ks * 16 + kq * 4);
#pragma unroll
                for (int dk = 0; dk < 4; dk++) {
                    float2 w = *(const float2*)(Wp + (kq * 4 + dk) * 64);
                    float e0 = (&q0.x)[dk], e1 = (&q1.x)[dk];
                    float e2 = (&q2.x)[dk], e3 = (&q3.x)[dk];
                    a0.x = fmaf(e0, w.x, a0.x); a0.y = fmaf(e0, w.y, a0.y);
                    a1.x = fmaf(e1, w.x, a1.x); a1.y = fmaf(e1, w.y, a1.y);
                    a2.x = fmaf(e2, w.x, a2.x); a2.y = fmaf(e2, w.y, a2.y);
                    a3.x = fmaf(e3, w.x, a3.x); a3.y = fmaf(e3, w.y, a3.y);
                }
            }
            float* rp = redk + ks * 512 + rb * 64 + c2;
            *(float2*)(rp)       = a0;
            *(float2*)(rp + 64)  = a1;
            *(float2*)(rp + 128) = a2;
            *(float2*)(rp + 192) = a3;
            __syncthreads();
            {
                int r = t >> 6, c = t & 63;
                float v = sBout[c];
#pragma unroll
                for (int ks2 = 0; ks2 < 8; ks2++) v += redk[ks2 * 512 + t];
                out[(size_t)(r0 + r) * 64 + c] = v;
            }
        }
    }
}

// =====================================================================
// launcher
// =====================================================================
extern "C" void kernel_launch(void* const* d_in, const int* in_sizes, int n_in,
                              void* d_out, int out_size)
{
    const float* x    = (const float*)d_in[0];
    const float* ew   = (const float*)d_in[2];
    const float* W1   = (const float*)d_in[4];
    const float* b1   = (const float*)d_in[5];
    const float* W2   = (const float*)d_in[6];
    const float* b2   = (const float*)d_in[7];
    const float* Wm0  = (const float*)d_in[8];
    const float* bm0  = (const float*)d_in[9];
    const float* g0   = (const float*)d_in[10];
    const float* be0  = (const float*)d_in[11];
    const float* Wm1  = (const float*)d_in[12];
    const float* bm1  = (const float*)d_in[13];
    const float* g1   = (const float*)d_in[14];
    const float* be1  = (const float*)d_in[15];
    const float* Wm2  = (const float*)d_in[16];
    const float* bm2  = (const float*)d_in[17];
    const float* g2   = (const float*)d_in[18];
    const float* be2  = (const float*)d_in[19];
    const float* Wout = (const float*)d_in[20];
    const float* bout = (const float*)d_in[21];
    float* out = (float*)d_out;

    const int SMEM_A = KA_SMEM_FLOATS * 4;   // 66816 B
    cudaFuncSetAttribute(kA, cudaFuncAttributeMaxDynamicSharedMemorySize, SMEM_A);
    cudaFuncSetAttribute(kB, cudaFuncAttributeMaxDynamicSharedMemorySize, KB_SMEM_BYTES);
    cudaFuncSetAttribute(kB, cudaFuncAttributeNonPortableClusterSizeAllowed, 1);

    kA<<<288, 256, SMEM_A>>>(x, ew, W1, b1, W2, b2, Wm0);

    cudaLaunchConfig_t cfg = {};
    cfg.gridDim = dim3(16, 1, 1);
    cfg.blockDim = dim3(512, 1, 1);
    cfg.dynamicSmemBytes = KB_SMEM_BYTES;
    cfg.stream = 0;
    int csize = 0;
    cudaError_t qerr = cudaOccupancyMaxPotentialClusterSize(&csize, kB, &cfg);
    if (qerr == cudaSuccess && csize >= 16) {
        cudaLaunchAttribute attrs[1];
        attrs[0].id = cudaLaunchAttributeClusterDimension;
        attrs[0].val.clusterDim.x = 16;
        attrs[0].val.clusterDim.y = 1;
        attrs[0].val.clusterDim.z = 1;
        cfg.attrs = attrs;
        cfg.numAttrs = 1;
        cudaLaunchKernelEx(&cfg, kB, bm0, g0, be0, Wm1, bm1, g1, be1,
                           Wm2, bm2, g2, be2, Wout, bout, out, 1);
    } else {
        kB<<<16, 512, KB_SMEM_BYTES>>>(bm0, g0, be0, Wm1, bm1, g1, be1,
                                       Wm2, bm2, g2, be2, Wout, bout, out, 0);
    }
}